// round 11
// baseline (speedup 1.0000x reference)
#include <cuda_runtime.h>
#include <cstdint>

// Dims: x [4,2048,2048] -> M=8192, K=2048; weight [8192,2048] -> N=8192, K=2048.
#define MDIM 8192
#define NDIM 8192
#define KDIM 2048

#define BM 64
#define BN 128
#define BK 64
#define KT (KDIM / BK)   // 32 k-tiles
#define NSTAGE 4
#define SPAD 80          // smem row stride bytes (64 data + 16 pad) -> conflict-free

#define A_BYTES (BM * SPAD)              // 5120
#define B_BYTES (BN * SPAD)              // 10240
#define STAGE_BYTES (A_BYTES + B_BYTES)  // 15360
#define SMEM_TOTAL (NSTAGE * STAGE_BYTES) // 61440 (x3 CTAs/SM = 184KB)

#define NWPART 1024      // weight abs partial blocks

// -------- scratch (static device globals; no runtime allocation) --------
__device__ signed char g_wq[(long)NDIM * KDIM];   // ternary weights as int8
__device__ signed char g_xq[(long)MDIM * KDIM];   // quantized activations
__device__ float       g_xinv[MDIM];              // per-row 1/x_scale
__device__ double      g_part[NWPART];

// ============================================================
// Kernel A: fused  (blocks [0,8192): x row quant — independent of mean)
//                  (blocks [8192, 8192+NWPART): weight |.| partial sums)
// ============================================================
__global__ void k_xquant_wabs(const float* __restrict__ x,
                              const float* __restrict__ w) {
    const int tid = threadIdx.x;
    if (blockIdx.x < MDIM) {
        const int row = blockIdx.x;
        const float4* xr = (const float4*)(x + (long)row * KDIM);
        float4 v0 = xr[tid];
        float4 v1 = xr[tid + 256];
        float m = fabsf(v0.x);
        m = fmaxf(m, fabsf(v0.y)); m = fmaxf(m, fabsf(v0.z)); m = fmaxf(m, fabsf(v0.w));
        m = fmaxf(m, fabsf(v1.x)); m = fmaxf(m, fabsf(v1.y));
        m = fmaxf(m, fabsf(v1.z)); m = fmaxf(m, fabsf(v1.w));
        #pragma unroll
        for (int o = 16; o > 0; o >>= 1)
            m = fmaxf(m, __shfl_xor_sync(0xffffffffu, m, o));
        __shared__ float sm[8];
        if ((tid & 31) == 0) sm[tid >> 5] = m;
        __syncthreads();
        float xmax = sm[0];
        #pragma unroll
        for (int i = 1; i < 8; ++i) xmax = fmaxf(xmax, sm[i]);

        const float scale = 127.0f / (xmax + 1e-8f);
        if (tid == 0) g_xinv[row] = 1.0f / scale;

        char4 q0, q1;
        q0.x = (signed char)__float2int_rn(v0.x * scale);
        q0.y = (signed char)__float2int_rn(v0.y * scale);
        q0.z = (signed char)__float2int_rn(v0.z * scale);
        q0.w = (signed char)__float2int_rn(v0.w * scale);
        q1.x = (signed char)__float2int_rn(v1.x * scale);
        q1.y = (signed char)__float2int_rn(v1.y * scale);
        q1.z = (signed char)__float2int_rn(v1.z * scale);
        q1.w = (signed char)__float2int_rn(v1.w * scale);
        char4* o4 = (char4*)(g_xq + (long)row * KDIM);
        o4[tid]       = q0;
        o4[tid + 256] = q1;
    } else {
        const int blk = blockIdx.x - MDIM;
        const float4* w4 = (const float4*)w;
        const long base = (long)blk * 4096;
        double s = 0.0;
        #pragma unroll
        for (int j = 0; j < 16; ++j) {
            float4 v = w4[base + j * 256 + tid];
            s += (double)fabsf(v.x) + (double)fabsf(v.y)
               + (double)fabsf(v.z) + (double)fabsf(v.w);
        }
        __shared__ double smd[256];
        smd[tid] = s;
        __syncthreads();
        for (int o = 128; o > 0; o >>= 1) {
            if (tid < o) smd[tid] += smd[tid + o];
            __syncthreads();
        }
        if (tid == 0) g_part[blk] = smd[0];
    }
}

// ============================================================
// Kernel B: in-block mean reduction (redundant, cheap) + ternarize
// ============================================================
__global__ void k_wquant(const float4* __restrict__ w4) {
    const int tid = threadIdx.x;
    double s = g_part[tid] + g_part[tid + 256]
             + g_part[tid + 512] + g_part[tid + 768];
    __shared__ double smd[256];
    smd[tid] = s;
    __syncthreads();
    for (int o = 128; o > 0; o >>= 1) {
        if (tid < o) smd[tid] += smd[tid + o];
        __syncthreads();
    }
    const float mean = (float)(smd[0] / ((double)NDIM * (double)KDIM));

    const long base = (long)blockIdx.x * 4096;
    char4* out4 = (char4*)g_wq;
    #pragma unroll
    for (int j = 0; j < 16; ++j) {
        const long idx = base + j * 256 + tid;
        float4 v = w4[idx];
        char4 q;
        q.x = (fabsf(v.x) > mean) ? (v.x > 0.f ? 1 : -1) : 0;
        q.y = (fabsf(v.y) > mean) ? (v.y > 0.f ? 1 : -1) : 0;
        q.z = (fabsf(v.z) > mean) ? (v.z > 0.f ? 1 : -1) : 0;
        q.w = (fabsf(v.w) > mean) ? (v.w > 0.f ? 1 : -1) : 0;
        out4[idx] = q;
    }
}

// ============================================================
// GEMM helpers
// ============================================================
__device__ __forceinline__ void mma_s8(int* c, const uint32_t* a,
                                       uint32_t b0, uint32_t b1) {
    asm volatile(
        "mma.sync.aligned.m16n8k32.row.col.s32.s8.s8.s32 "
        "{%0,%1,%2,%3}, {%4,%5,%6,%7}, {%8,%9}, {%0,%1,%2,%3};\n"
        : "+r"(c[0]), "+r"(c[1]), "+r"(c[2]), "+r"(c[3])
        : "r"(a[0]), "r"(a[1]), "r"(a[2]), "r"(a[3]), "r"(b0), "r"(b1));
}

__device__ __forceinline__ void ldsm4(uint32_t& r0, uint32_t& r1,
                                      uint32_t& r2, uint32_t& r3, uint32_t addr) {
    asm volatile(
        "ldmatrix.sync.aligned.m8n8.x4.shared.b16 {%0,%1,%2,%3}, [%4];\n"
        : "=r"(r0), "=r"(r1), "=r"(r2), "=r"(r3) : "r"(addr));
}

__device__ __forceinline__ void cp16(uint32_t s, const void* g) {
    asm volatile("cp.async.cg.shared.global [%0], [%1], 16;\n" :: "r"(s), "l"(g));
}

// ============================================================
// GEMM: int8 mma.sync, 64x128 CTA tile, 256 thr, 3 CTAs/SM,
//       warp tile 32x32, BK=64, 4-stage cp.async
// ============================================================
__global__ __launch_bounds__(256, 3)
void k_gemm_s8(const float* __restrict__ wscale, float* __restrict__ out) {
    extern __shared__ signed char dsm[];

    const int tid  = threadIdx.x;
    const int lane = tid & 31;
    const int warp = tid >> 5;
    const int wm   = warp & 1;   // 0..1 -> 32-row half
    const int wn   = warp >> 1;  // 0..3 -> 32-col group

    const int bM = blockIdx.y * BM;
    const int bN = blockIdx.x * BN;

    // ---- cp.async plan: 256 chunks A + 512 chunks B (16B) per tile, 3/thread ----
    const int r0 = tid >> 2;          // 0..63
    const int cB = (tid & 3) * 16;
    const signed char* gA  = g_xq + (long)(bM + r0)      * KDIM + cB;
    const signed char* gB0 = g_wq + (long)(bN + r0)      * KDIM + cB;
    const signed char* gB1 = g_wq + (long)(bN + r0 + 64) * KDIM + cB;
    const int sA  = r0 * SPAD + cB;
    const int sB0 = A_BYTES + r0 * SPAD + cB;
    const int sB1 = A_BYTES + (r0 + 64) * SPAD + cB;

    const uint32_t smem = (uint32_t)__cvta_generic_to_shared(dsm);

    // ---- ldmatrix per-lane offsets ----
    const int lrow = (lane & 7) + ((lane >> 3) & 1) * 8;
    const int lcol = (lane >> 4) * 16;
    int aoff[2], boff[2];
    #pragma unroll
    for (int mi = 0; mi < 2; ++mi)
        aoff[mi] = (wm * 32 + mi * 16 + lrow) * SPAD + lcol;
    #pragma unroll
    for (int p = 0; p < 2; ++p)
        boff[p] = A_BYTES + (wn * 32 + p * 16 + lrow) * SPAD + lcol;

    // ---- prefetch first NSTAGE-1 tiles ----
    #pragma unroll
    for (int t = 0; t < NSTAGE - 1; ++t) {
        const uint32_t sb = smem + t * STAGE_BYTES;
        const long koff = (long)t * BK;
        cp16(sb + sA,  gA  + koff);
        cp16(sb + sB0, gB0 + koff);
        cp16(sb + sB1, gB1 + koff);
        asm volatile("cp.async.commit_group;\n");
    }

    int c[2][4][4];
    #pragma unroll
    for (int mi = 0; mi < 2; ++mi)
        #pragma unroll
        for (int ni = 0; ni < 4; ++ni)
            #pragma unroll
            for (int r = 0; r < 4; ++r) c[mi][ni][r] = 0;

    for (int kt = 0; kt < KT; ++kt) {
        asm volatile("cp.async.wait_group %0;\n" :: "n"(NSTAGE - 2));
        __syncthreads();

        if (kt + NSTAGE - 1 < KT) {
            const int nt = kt + NSTAGE - 1;
            const uint32_t sb = smem + (nt & (NSTAGE - 1)) * STAGE_BYTES;
            const long koff = (long)nt * BK;
            cp16(sb + sA,  gA  + koff);
            cp16(sb + sB0, gB0 + koff);
            cp16(sb + sB1, gB1 + koff);
            asm volatile("cp.async.commit_group;\n");
        }

        const uint32_t base = smem + (kt & (NSTAGE - 1)) * STAGE_BYTES;

        #pragma unroll
        for (int ks = 0; ks < 2; ++ks) {
            const int kadd = ks * 32;
            uint32_t a[2][4], b[2][4];
            #pragma unroll
            for (int mi = 0; mi < 2; ++mi)
                ldsm4(a[mi][0], a[mi][1], a[mi][2], a[mi][3],
                      base + aoff[mi] + kadd);
            #pragma unroll
            for (int p = 0; p < 2; ++p)
                ldsm4(b[p][0], b[p][1], b[p][2], b[p][3],
                      base + boff[p] + kadd);
            // pair p covers ni=2p (regs 0,2) and ni=2p+1 (regs 1,3)
            #pragma unroll
            for (int mi = 0; mi < 2; ++mi) {
                #pragma unroll
                for (int p = 0; p < 2; ++p) {
                    mma_s8(c[mi][2 * p],     a[mi], b[p][0], b[p][2]);
                    mma_s8(c[mi][2 * p + 1], a[mi], b[p][1], b[p][3]);
                }
            }
        }
    }

    // ---- epilogue: out = c * weight_scale * (1/x_scale[row]) ----
    const float ws = *wscale;
    #pragma unroll
    for (int mi = 0; mi < 2; ++mi) {
        const int row = bM + wm * 32 + mi * 16 + (lane >> 2);
        const float s0 = ws * g_xinv[row];
        const float s1 = ws * g_xinv[row + 8];
        #pragma unroll
        for (int ni = 0; ni < 4; ++ni) {
            const int col = bN + wn * 32 + ni * 8 + (lane & 3) * 2;
            float2 v0, v1;
            v0.x = (float)c[mi][ni][0] * s0;
            v0.y = (float)c[mi][ni][1] * s0;
            v1.x = (float)c[mi][ni][2] * s1;
            v1.y = (float)c[mi][ni][3] * s1;
            *(float2*)(out + (long)row       * NDIM + col) = v0;
            *(float2*)(out + (long)(row + 8) * NDIM + col) = v1;
        }
    }
}

// ============================================================
// launch
// ============================================================
extern "C" void kernel_launch(void* const* d_in, const int* in_sizes, int n_in,
                              void* d_out, int out_size) {
    const float* x      = (const float*)d_in[0];
    const float* w      = (const float*)d_in[1];
    const float* wscale = (const float*)d_in[2];
    float* out = (float*)d_out;

    k_xquant_wabs<<<MDIM + NWPART, 256>>>(x, w);
    k_wquant<<<1024, 256>>>((const float4*)w);

    cudaFuncSetAttribute(k_gemm_s8, cudaFuncAttributeMaxDynamicSharedMemorySize,
                         SMEM_TOTAL);
    dim3 grid(NDIM / BN, MDIM / BM);  // 64 x 128
    k_gemm_s8<<<grid, 256, SMEM_TOTAL>>>(wscale, out);
}

// round 12
// speedup vs baseline: 1.0196x; 1.0196x over previous
#include <cuda_runtime.h>
#include <cstdint>

// Dims: x [4,2048,2048] -> M=8192, K=2048; weight [8192,2048] -> N=8192, K=2048.
#define MDIM 8192
#define NDIM 8192
#define KDIM 2048

#define BM 128
#define BN 128
#define BK 64
#define KT (KDIM / BK)   // 32 k-tiles
#define NSTAGE 4
#define SPAD 80          // smem row stride bytes (64 data + 16 pad) -> conflict-free

#define A_BYTES (BM * SPAD)              // 10240
#define B_BYTES (BN * SPAD)              // 10240
#define STAGE_BYTES (A_BYTES + B_BYTES)  // 20480
#define SMEM_TOTAL (NSTAGE * STAGE_BYTES) // 81920 (x2 CTAs/SM = 160KB)

#define NWPART 1024      // weight abs partial blocks

// -------- scratch (static device globals; no runtime allocation) --------
__device__ signed char g_wq[(long)NDIM * KDIM];   // ternary weights as int8
__device__ signed char g_xq[(long)MDIM * KDIM];   // quantized activations
__device__ float       g_xinv[MDIM];              // per-row 1/x_scale
__device__ double      g_part[NWPART];

// ============================================================
// Kernel 1: weight |.| partial sums (4 independent double accums)
// ============================================================
__global__ void k_wabs(const float* __restrict__ w) {
    const int tid = threadIdx.x;
    const float4* w4 = (const float4*)w;
    const long base = (long)blockIdx.x * 4096;   // 4096 float4 per block
    double s0 = 0.0, s1 = 0.0, s2 = 0.0, s3 = 0.0;
    #pragma unroll
    for (int j = 0; j < 16; ++j) {
        float4 v = w4[base + j * 256 + tid];
        s0 += (double)fabsf(v.x);
        s1 += (double)fabsf(v.y);
        s2 += (double)fabsf(v.z);
        s3 += (double)fabsf(v.w);
    }
    __shared__ double smd[256];
    smd[tid] = (s0 + s1) + (s2 + s3);
    __syncthreads();
    for (int o = 128; o > 0; o >>= 1) {
        if (tid < o) smd[tid] += smd[tid + o];
        __syncthreads();
    }
    if (tid == 0) g_part[blockIdx.x] = smd[0];
}

// ============================================================
// Kernel 2: fused  blocks [0,1024): mean-reduce (redundant) + ternarize
//                  blocks [1024, 1024+8192): x row quant
// Heavy ternarize blocks first for better wave packing.
// ============================================================
__global__ void k_quant_fused(const float* __restrict__ x,
                              const float4* __restrict__ w4) {
    const int tid = threadIdx.x;
    if (blockIdx.x < NWPART) {
        // ---- reduce NWPART partials, then ternarize this chunk ----
        double s = g_part[tid] + g_part[tid + 256]
                 + g_part[tid + 512] + g_part[tid + 768];
        __shared__ double smd[256];
        smd[tid] = s;
        __syncthreads();
        for (int o = 128; o > 0; o >>= 1) {
            if (tid < o) smd[tid] += smd[tid + o];
            __syncthreads();
        }
        const float mean = (float)(smd[0] / ((double)NDIM * (double)KDIM));

        const long base = (long)blockIdx.x * 4096;
        char4* out4 = (char4*)g_wq;
        #pragma unroll
        for (int j = 0; j < 16; ++j) {
            const long idx = base + j * 256 + tid;
            float4 v = w4[idx];
            char4 q;
            q.x = (fabsf(v.x) > mean) ? (v.x > 0.f ? 1 : -1) : 0;
            q.y = (fabsf(v.y) > mean) ? (v.y > 0.f ? 1 : -1) : 0;
            q.z = (fabsf(v.z) > mean) ? (v.z > 0.f ? 1 : -1) : 0;
            q.w = (fabsf(v.w) > mean) ? (v.w > 0.f ? 1 : -1) : 0;
            out4[idx] = q;
        }
    } else {
        // ---- x row quant ----
        const int row = blockIdx.x - NWPART;
        const float4* xr = (const float4*)(x + (long)row * KDIM);
        float4 v0 = xr[tid];
        float4 v1 = xr[tid + 256];
        float m = fabsf(v0.x);
        m = fmaxf(m, fabsf(v0.y)); m = fmaxf(m, fabsf(v0.z)); m = fmaxf(m, fabsf(v0.w));
        m = fmaxf(m, fabsf(v1.x)); m = fmaxf(m, fabsf(v1.y));
        m = fmaxf(m, fabsf(v1.z)); m = fmaxf(m, fabsf(v1.w));
        #pragma unroll
        for (int o = 16; o > 0; o >>= 1)
            m = fmaxf(m, __shfl_xor_sync(0xffffffffu, m, o));
        __shared__ float sm[8];
        if ((tid & 31) == 0) sm[tid >> 5] = m;
        __syncthreads();
        float xmax = sm[0];
        #pragma unroll
        for (int i = 1; i < 8; ++i) xmax = fmaxf(xmax, sm[i]);

        const float scale = 127.0f / (xmax + 1e-8f);
        if (tid == 0) g_xinv[row] = 1.0f / scale;

        char4 q0, q1;
        q0.x = (signed char)__float2int_rn(v0.x * scale);
        q0.y = (signed char)__float2int_rn(v0.y * scale);
        q0.z = (signed char)__float2int_rn(v0.z * scale);
        q0.w = (signed char)__float2int_rn(v0.w * scale);
        q1.x = (signed char)__float2int_rn(v1.x * scale);
        q1.y = (signed char)__float2int_rn(v1.y * scale);
        q1.z = (signed char)__float2int_rn(v1.z * scale);
        q1.w = (signed char)__float2int_rn(v1.w * scale);
        char4* o4 = (char4*)(g_xq + (long)row * KDIM);
        o4[tid]       = q0;
        o4[tid + 256] = q1;
    }
}

// ============================================================
// GEMM helpers
// ============================================================
__device__ __forceinline__ void mma_s8(int* c, const uint32_t* a,
                                       uint32_t b0, uint32_t b1) {
    asm volatile(
        "mma.sync.aligned.m16n8k32.row.col.s32.s8.s8.s32 "
        "{%0,%1,%2,%3}, {%4,%5,%6,%7}, {%8,%9}, {%0,%1,%2,%3};\n"
        : "+r"(c[0]), "+r"(c[1]), "+r"(c[2]), "+r"(c[3])
        : "r"(a[0]), "r"(a[1]), "r"(a[2]), "r"(a[3]), "r"(b0), "r"(b1));
}

__device__ __forceinline__ void ldsm4(uint32_t& r0, uint32_t& r1,
                                      uint32_t& r2, uint32_t& r3, uint32_t addr) {
    asm volatile(
        "ldmatrix.sync.aligned.m8n8.x4.shared.b16 {%0,%1,%2,%3}, [%4];\n"
        : "=r"(r0), "=r"(r1), "=r"(r2), "=r"(r3) : "r"(addr));
}

__device__ __forceinline__ void cp16(uint32_t s, const void* g) {
    asm volatile("cp.async.cg.shared.global [%0], [%1], 16;\n" :: "r"(s), "l"(g));
}

// ============================================================
// GEMM: int8 mma.sync, 128x128 tile, 256 thr, 2 CTAs/SM,
//       warp tile 64x32, BK=64, 4-stage cp.async (proven 505us config)
// ============================================================
__global__ __launch_bounds__(256, 2)
void k_gemm_s8(const float* __restrict__ wscale, float* __restrict__ out) {
    extern __shared__ signed char dsm[];

    const int tid  = threadIdx.x;
    const int lane = tid & 31;
    const int warp = tid >> 5;
    const int wm   = warp & 1;   // 0..1 -> 64 rows
    const int wn   = warp >> 1;  // 0..3 -> 32 cols

    const int bM = blockIdx.y * BM;
    const int bN = blockIdx.x * BN;

    // ---- cp.async plan: 512 chunks A + 512 chunks B (16B each) per tile ----
    const int r0 = tid >> 2;          // 0..63
    const int cB = (tid & 3) * 16;
    const signed char* gA0 = g_xq + (long)(bM + r0)      * KDIM + cB;
    const signed char* gA1 = g_xq + (long)(bM + r0 + 64) * KDIM + cB;
    const signed char* gB0 = g_wq + (long)(bN + r0)      * KDIM + cB;
    const signed char* gB1 = g_wq + (long)(bN + r0 + 64) * KDIM + cB;
    const int sOff0 = r0 * SPAD + cB;
    const int sOff1 = (r0 + 64) * SPAD + cB;

    const uint32_t smem = (uint32_t)__cvta_generic_to_shared(dsm);

    // ---- ldmatrix per-lane offsets ----
    const int lrow = (lane & 7) + ((lane >> 3) & 1) * 8;
    const int lcol = (lane >> 4) * 16;
    int aoff[4], boff[2];
    #pragma unroll
    for (int mi = 0; mi < 4; ++mi)
        aoff[mi] = (wm * 64 + mi * 16 + lrow) * SPAD + lcol;
    #pragma unroll
    for (int p = 0; p < 2; ++p)
        boff[p] = A_BYTES + (wn * 32 + p * 16 + lrow) * SPAD + lcol;

    // ---- prefetch first NSTAGE-1 tiles ----
    #pragma unroll
    for (int t = 0; t < NSTAGE - 1; ++t) {
        const uint32_t sb = smem + t * STAGE_BYTES;
        const long koff = (long)t * BK;
        cp16(sb + sOff0, gA0 + koff);
        cp16(sb + sOff1, gA1 + koff);
        cp16(sb + A_BYTES + sOff0, gB0 + koff);
        cp16(sb + A_BYTES + sOff1, gB1 + koff);
        asm volatile("cp.async.commit_group;\n");
    }

    int c[4][4][4];
    #pragma unroll
    for (int mi = 0; mi < 4; ++mi)
        #pragma unroll
        for (int ni = 0; ni < 4; ++ni)
            #pragma unroll
            for (int r = 0; r < 4; ++r) c[mi][ni][r] = 0;

    for (int kt = 0; kt < KT; ++kt) {
        asm volatile("cp.async.wait_group %0;\n" :: "n"(NSTAGE - 2));
        __syncthreads();

        if (kt + NSTAGE - 1 < KT) {
            const int nt = kt + NSTAGE - 1;
            const uint32_t sb = smem + (nt & (NSTAGE - 1)) * STAGE_BYTES;
            const long koff = (long)nt * BK;
            cp16(sb + sOff0, gA0 + koff);
            cp16(sb + sOff1, gA1 + koff);
            cp16(sb + A_BYTES + sOff0, gB0 + koff);
            cp16(sb + A_BYTES + sOff1, gB1 + koff);
            asm volatile("cp.async.commit_group;\n");
        }

        const uint32_t base = smem + (kt & (NSTAGE - 1)) * STAGE_BYTES;

        #pragma unroll
        for (int ks = 0; ks < 2; ++ks) {
            const int kadd = ks * 32;
            uint32_t a[4][4], b[2][4];
            #pragma unroll
            for (int mi = 0; mi < 4; ++mi)
                ldsm4(a[mi][0], a[mi][1], a[mi][2], a[mi][3],
                      base + aoff[mi] + kadd);
            #pragma unroll
            for (int p = 0; p < 2; ++p)
                ldsm4(b[p][0], b[p][1], b[p][2], b[p][3],
                      base + boff[p] + kadd);
            // pair p covers ni=2p (regs 0,2) and ni=2p+1 (regs 1,3)
            #pragma unroll
            for (int mi = 0; mi < 4; ++mi) {
                #pragma unroll
                for (int p = 0; p < 2; ++p) {
                    mma_s8(c[mi][2 * p],     a[mi], b[p][0], b[p][2]);
                    mma_s8(c[mi][2 * p + 1], a[mi], b[p][1], b[p][3]);
                }
            }
        }
    }

    // ---- epilogue: out = c * weight_scale * (1/x_scale[row]) ----
    const float ws = *wscale;
    #pragma unroll
    for (int mi = 0; mi < 4; ++mi) {
        const int row = bM + wm * 64 + mi * 16 + (lane >> 2);
        const float s0 = ws * g_xinv[row];
        const float s1 = ws * g_xinv[row + 8];
        #pragma unroll
        for (int ni = 0; ni < 4; ++ni) {
            const int col = bN + wn * 32 + ni * 8 + (lane & 3) * 2;
            float2 v0, v1;
            v0.x = (float)c[mi][ni][0] * s0;
            v0.y = (float)c[mi][ni][1] * s0;
            v1.x = (float)c[mi][ni][2] * s1;
            v1.y = (float)c[mi][ni][3] * s1;
            *(float2*)(out + (long)row       * NDIM + col) = v0;
            *(float2*)(out + (long)(row + 8) * NDIM + col) = v1;
        }
    }
}

// ============================================================
// launch
// ============================================================
extern "C" void kernel_launch(void* const* d_in, const int* in_sizes, int n_in,
                              void* d_out, int out_size) {
    const float* x      = (const float*)d_in[0];
    const float* w      = (const float*)d_in[1];
    const float* wscale = (const float*)d_in[2];
    float* out = (float*)d_out;

    k_wabs<<<NWPART, 256>>>(w);
    k_quant_fused<<<NWPART + MDIM, 256>>>(x, (const float4*)w);

    cudaFuncSetAttribute(k_gemm_s8, cudaFuncAttributeMaxDynamicSharedMemorySize,
                         SMEM_TOTAL);
    dim3 grid(NDIM / BN, MDIM / BM);  // 64 x 64
    k_gemm_s8<<<grid, 256, SMEM_TOTAL>>>(wscale, out);
}

// round 13
// speedup vs baseline: 1.0228x; 1.0031x over previous
#include <cuda_runtime.h>
#include <cstdint>

// Dims: x [4,2048,2048] -> M=8192, K=2048; weight [8192,2048] -> N=8192, K=2048.
#define MDIM 8192
#define NDIM 8192
#define KDIM 2048

#define BM 128
#define BN 128
#define BK 64
#define KT (KDIM / BK)   // 32 k-tiles
#define NSTAGE 4
#define SPAD 80          // smem row stride bytes (64 data + 16 pad) -> conflict-free

#define A_BYTES (BM * SPAD)              // 10240
#define B_BYTES (BN * SPAD)              // 10240
#define STAGE_BYTES (A_BYTES + B_BYTES)  // 20480
#define SMEM_TOTAL (NSTAGE * STAGE_BYTES) // 81920 (x2 CTAs/SM = 160KB)

#define NWPART 2048      // weight abs partial blocks

// -------- scratch (static device globals; no runtime allocation) --------
__device__ signed char g_wq[(long)NDIM * KDIM];   // ternary weights as int8
__device__ signed char g_xq[(long)MDIM * KDIM];   // quantized activations
__device__ float       g_xinv[MDIM];              // per-row 1/x_scale
__device__ double      g_part[NWPART];

// ============================================================
// Kernel 1: weight |.| partial sums.
// 2048 blocks x 256 thr x 8 float4. Loads batched 4-wide; 4
// independent double accumulators -> short (8-deep) DADD chains.
// ============================================================
__global__ void k_wabs(const float* __restrict__ w) {
    const int tid = threadIdx.x;
    const float4* w4 = (const float4*)w;
    const long base = (long)blockIdx.x * 2048;   // 2048 float4 per block
    double s0 = 0.0, s1 = 0.0, s2 = 0.0, s3 = 0.0;
    #pragma unroll
    for (int j = 0; j < 2; ++j) {
        // batch 4 independent loads, then accumulate
        float4 v0 = w4[base + (j * 4 + 0) * 256 + tid];
        float4 v1 = w4[base + (j * 4 + 1) * 256 + tid];
        float4 v2 = w4[base + (j * 4 + 2) * 256 + tid];
        float4 v3 = w4[base + (j * 4 + 3) * 256 + tid];
        s0 += (double)fabsf(v0.x); s1 += (double)fabsf(v0.y);
        s2 += (double)fabsf(v0.z); s3 += (double)fabsf(v0.w);
        s0 += (double)fabsf(v1.x); s1 += (double)fabsf(v1.y);
        s2 += (double)fabsf(v1.z); s3 += (double)fabsf(v1.w);
        s0 += (double)fabsf(v2.x); s1 += (double)fabsf(v2.y);
        s2 += (double)fabsf(v2.z); s3 += (double)fabsf(v2.w);
        s0 += (double)fabsf(v3.x); s1 += (double)fabsf(v3.y);
        s2 += (double)fabsf(v3.z); s3 += (double)fabsf(v3.w);
    }
    __shared__ double smd[256];
    smd[tid] = (s0 + s1) + (s2 + s3);
    __syncthreads();
    for (int o = 128; o > 0; o >>= 1) {
        if (tid < o) smd[tid] += smd[tid + o];
        __syncthreads();
    }
    if (tid == 0) g_part[blockIdx.x] = smd[0];
}

// ============================================================
// Kernel 2: fused  blocks [0,1024): mean-reduce (redundant) + ternarize
//                  blocks [1024, 1024+8192): x row quant
// ============================================================
__global__ void k_quant_fused(const float* __restrict__ x,
                              const float4* __restrict__ w4) {
    const int tid = threadIdx.x;
    if (blockIdx.x < 1024) {
        // ---- reduce NWPART=2048 partials, then ternarize this chunk ----
        double s = (g_part[tid]        + g_part[tid + 256])
                 + (g_part[tid + 512]  + g_part[tid + 768])
                 + (g_part[tid + 1024] + g_part[tid + 1280])
                 + (g_part[tid + 1536] + g_part[tid + 1792]);
        __shared__ double smd[256];
        smd[tid] = s;
        __syncthreads();
        for (int o = 128; o > 0; o >>= 1) {
            if (tid < o) smd[tid] += smd[tid + o];
            __syncthreads();
        }
        const float mean = (float)(smd[0] / ((double)NDIM * (double)KDIM));

        const long base = (long)blockIdx.x * 4096;
        char4* out4 = (char4*)g_wq;
        #pragma unroll
        for (int j = 0; j < 16; ++j) {
            const long idx = base + j * 256 + tid;
            float4 v = w4[idx];
            char4 q;
            q.x = (fabsf(v.x) > mean) ? (v.x > 0.f ? 1 : -1) : 0;
            q.y = (fabsf(v.y) > mean) ? (v.y > 0.f ? 1 : -1) : 0;
            q.z = (fabsf(v.z) > mean) ? (v.z > 0.f ? 1 : -1) : 0;
            q.w = (fabsf(v.w) > mean) ? (v.w > 0.f ? 1 : -1) : 0;
            out4[idx] = q;
        }
    } else {
        // ---- x row quant ----
        const int row = blockIdx.x - 1024;
        const float4* xr = (const float4*)(x + (long)row * KDIM);
        float4 v0 = xr[tid];
        float4 v1 = xr[tid + 256];
        float m = fabsf(v0.x);
        m = fmaxf(m, fabsf(v0.y)); m = fmaxf(m, fabsf(v0.z)); m = fmaxf(m, fabsf(v0.w));
        m = fmaxf(m, fabsf(v1.x)); m = fmaxf(m, fabsf(v1.y));
        m = fmaxf(m, fabsf(v1.z)); m = fmaxf(m, fabsf(v1.w));
        #pragma unroll
        for (int o = 16; o > 0; o >>= 1)
            m = fmaxf(m, __shfl_xor_sync(0xffffffffu, m, o));
        __shared__ float sm[8];
        if ((tid & 31) == 0) sm[tid >> 5] = m;
        __syncthreads();
        float xmax = sm[0];
        #pragma unroll
        for (int i = 1; i < 8; ++i) xmax = fmaxf(xmax, sm[i]);

        const float scale = 127.0f / (xmax + 1e-8f);
        if (tid == 0) g_xinv[row] = 1.0f / scale;

        char4 q0, q1;
        q0.x = (signed char)__float2int_rn(v0.x * scale);
        q0.y = (signed char)__float2int_rn(v0.y * scale);
        q0.z = (signed char)__float2int_rn(v0.z * scale);
        q0.w = (signed char)__float2int_rn(v0.w * scale);
        q1.x = (signed char)__float2int_rn(v1.x * scale);
        q1.y = (signed char)__float2int_rn(v1.y * scale);
        q1.z = (signed char)__float2int_rn(v1.z * scale);
        q1.w = (signed char)__float2int_rn(v1.w * scale);
        char4* o4 = (char4*)(g_xq + (long)row * KDIM);
        o4[tid]       = q0;
        o4[tid + 256] = q1;
    }
}

// ============================================================
// GEMM helpers
// ============================================================
__device__ __forceinline__ void mma_s8(int* c, const uint32_t* a,
                                       uint32_t b0, uint32_t b1) {
    asm volatile(
        "mma.sync.aligned.m16n8k32.row.col.s32.s8.s8.s32 "
        "{%0,%1,%2,%3}, {%4,%5,%6,%7}, {%8,%9}, {%0,%1,%2,%3};\n"
        : "+r"(c[0]), "+r"(c[1]), "+r"(c[2]), "+r"(c[3])
        : "r"(a[0]), "r"(a[1]), "r"(a[2]), "r"(a[3]), "r"(b0), "r"(b1));
}

__device__ __forceinline__ void ldsm4(uint32_t& r0, uint32_t& r1,
                                      uint32_t& r2, uint32_t& r3, uint32_t addr) {
    asm volatile(
        "ldmatrix.sync.aligned.m8n8.x4.shared.b16 {%0,%1,%2,%3}, [%4];\n"
        : "=r"(r0), "=r"(r1), "=r"(r2), "=r"(r3) : "r"(addr));
}

__device__ __forceinline__ void cp16(uint32_t s, const void* g) {
    asm volatile("cp.async.cg.shared.global [%0], [%1], 16;\n" :: "r"(s), "l"(g));
}

// ============================================================
// GEMM: int8 mma.sync, 128x128 tile, 256 thr, 2 CTAs/SM,
//       warp tile 64x32, BK=64, 4-stage cp.async (proven 505us config)
// ============================================================
__global__ __launch_bounds__(256, 2)
void k_gemm_s8(const float* __restrict__ wscale, float* __restrict__ out) {
    extern __shared__ signed char dsm[];

    const int tid  = threadIdx.x;
    const int lane = tid & 31;
    const int warp = tid >> 5;
    const int wm   = warp & 1;   // 0..1 -> 64 rows
    const int wn   = warp >> 1;  // 0..3 -> 32 cols

    const int bM = blockIdx.y * BM;
    const int bN = blockIdx.x * BN;

    // ---- cp.async plan: 512 chunks A + 512 chunks B (16B each) per tile ----
    const int r0 = tid >> 2;          // 0..63
    const int cB = (tid & 3) * 16;
    const signed char* gA0 = g_xq + (long)(bM + r0)      * KDIM + cB;
    const signed char* gA1 = g_xq + (long)(bM + r0 + 64) * KDIM + cB;
    const signed char* gB0 = g_wq + (long)(bN + r0)      * KDIM + cB;
    const signed char* gB1 = g_wq + (long)(bN + r0 + 64) * KDIM + cB;
    const int sOff0 = r0 * SPAD + cB;
    const int sOff1 = (r0 + 64) * SPAD + cB;

    const uint32_t smem = (uint32_t)__cvta_generic_to_shared(dsm);

    // ---- ldmatrix per-lane offsets ----
    const int lrow = (lane & 7) + ((lane >> 3) & 1) * 8;
    const int lcol = (lane >> 4) * 16;
    int aoff[4], boff[2];
    #pragma unroll
    for (int mi = 0; mi < 4; ++mi)
        aoff[mi] = (wm * 64 + mi * 16 + lrow) * SPAD + lcol;
    #pragma unroll
    for (int p = 0; p < 2; ++p)
        boff[p] = A_BYTES + (wn * 32 + p * 16 + lrow) * SPAD + lcol;

    // ---- prefetch first NSTAGE-1 tiles ----
    #pragma unroll
    for (int t = 0; t < NSTAGE - 1; ++t) {
        const uint32_t sb = smem + t * STAGE_BYTES;
        const long koff = (long)t * BK;
        cp16(sb + sOff0, gA0 + koff);
        cp16(sb + sOff1, gA1 + koff);
        cp16(sb + A_BYTES + sOff0, gB0 + koff);
        cp16(sb + A_BYTES + sOff1, gB1 + koff);
        asm volatile("cp.async.commit_group;\n");
    }

    int c[4][4][4];
    #pragma unroll
    for (int mi = 0; mi < 4; ++mi)
        #pragma unroll
        for (int ni = 0; ni < 4; ++ni)
            #pragma unroll
            for (int r = 0; r < 4; ++r) c[mi][ni][r] = 0;

    for (int kt = 0; kt < KT; ++kt) {
        asm volatile("cp.async.wait_group %0;\n" :: "n"(NSTAGE - 2));
        __syncthreads();

        if (kt + NSTAGE - 1 < KT) {
            const int nt = kt + NSTAGE - 1;
            const uint32_t sb = smem + (nt & (NSTAGE - 1)) * STAGE_BYTES;
            const long koff = (long)nt * BK;
            cp16(sb + sOff0, gA0 + koff);
            cp16(sb + sOff1, gA1 + koff);
            cp16(sb + A_BYTES + sOff0, gB0 + koff);
            cp16(sb + A_BYTES + sOff1, gB1 + koff);
            asm volatile("cp.async.commit_group;\n");
        }

        const uint32_t base = smem + (kt & (NSTAGE - 1)) * STAGE_BYTES;

        #pragma unroll
        for (int ks = 0; ks < 2; ++ks) {
            const int kadd = ks * 32;
            uint32_t a[4][4], b[2][4];
            #pragma unroll
            for (int mi = 0; mi < 4; ++mi)
                ldsm4(a[mi][0], a[mi][1], a[mi][2], a[mi][3],
                      base + aoff[mi] + kadd);
            #pragma unroll
            for (int p = 0; p < 2; ++p)
                ldsm4(b[p][0], b[p][1], b[p][2], b[p][3],
                      base + boff[p] + kadd);
            // pair p covers ni=2p (regs 0,2) and ni=2p+1 (regs 1,3)
            #pragma unroll
            for (int mi = 0; mi < 4; ++mi) {
                #pragma unroll
                for (int p = 0; p < 2; ++p) {
                    mma_s8(c[mi][2 * p],     a[mi], b[p][0], b[p][2]);
                    mma_s8(c[mi][2 * p + 1], a[mi], b[p][1], b[p][3]);
                }
            }
        }
    }

    // ---- epilogue: out = c * weight_scale * (1/x_scale[row]), streaming stores ----
    const float ws = *wscale;
    #pragma unroll
    for (int mi = 0; mi < 4; ++mi) {
        const int row = bM + wm * 64 + mi * 16 + (lane >> 2);
        const float s0 = ws * g_xinv[row];
        const float s1 = ws * g_xinv[row + 8];
        #pragma unroll
        for (int ni = 0; ni < 4; ++ni) {
            const int col = bN + wn * 32 + ni * 8 + (lane & 3) * 2;
            float2 v0, v1;
            v0.x = (float)c[mi][ni][0] * s0;
            v0.y = (float)c[mi][ni][1] * s0;
            v1.x = (float)c[mi][ni][2] * s1;
            v1.y = (float)c[mi][ni][3] * s1;
            __stcs((float2*)(out + (long)row       * NDIM + col), v0);
            __stcs((float2*)(out + (long)(row + 8) * NDIM + col), v1);
        }
    }
}

// ============================================================
// launch
// ============================================================
extern "C" void kernel_launch(void* const* d_in, const int* in_sizes, int n_in,
                              void* d_out, int out_size) {
    const float* x      = (const float*)d_in[0];
    const float* w      = (const float*)d_in[1];
    const float* wscale = (const float*)d_in[2];
    float* out = (float*)d_out;

    k_wabs<<<NWPART, 256>>>(w);
    k_quant_fused<<<1024 + MDIM, 256>>>(x, (const float4*)w);

    cudaFuncSetAttribute(k_gemm_s8, cudaFuncAttributeMaxDynamicSharedMemorySize,
                         SMEM_TOTAL);
    dim3 grid(NDIM / BN, MDIM / BM);  // 64 x 64
    k_gemm_s8<<<grid, 256, SMEM_TOTAL>>>(wscale, out);
}